// round 13
// baseline (speedup 1.0000x reference)
#include <cuda_runtime.h>
#include <cuda_bf16.h>
#include <math.h>
#include <float.h>

#define NN 100000
#define FIN 50
#define CC 32
#define CAP 96

typedef unsigned long long u64;

// ---------------- scratch ----------------
__device__ int g_cnt[NN];
__device__ int g_badj[NN * CAP];
__device__ float g_agg1[NN * FIN];
__device__ float g_agg[NN * CC];
__device__ float g_ha[NN * CC];
__device__ float g_hb[NN * CC];

__device__ __forceinline__ u64 ffma2(u64 a, u64 b, u64 c) {
    u64 d;
    asm("fma.rn.f32x2 %0, %1, %2, %3;" : "=l"(d) : "l"(a), "l"(b), "l"(c));
    return d;
}
__device__ __forceinline__ void unpack2(u64 v, float& lo, float& hi) {
    unsigned int a, b;
    asm("mov.b64 {%0, %1}, %2;" : "=r"(a), "=r"(b) : "l"(v));
    lo = __uint_as_float(a);
    hi = __uint_as_float(b);
}

__global__ void __launch_bounds__(256) zero_cnt() {
    int i = blockIdx.x * blockDim.x + threadIdx.x;
    if (i < NN) g_cnt[i] = 0;
}

__global__ void __launch_bounds__(256) bucket_scatter(const int* __restrict__ ei, int E) {
    int e = blockIdx.x * blockDim.x + threadIdx.x;
    if (e >= E) return;
    int s = ei[e];
    int d = ei[E + e];
    int pos = atomicAdd(&g_cnt[d], 1);
    if (pos < CAP) g_badj[d * CAP + pos] = s;
}

// ---------------- gather-max d=50 -> g_agg1 ----------------
__global__ void __launch_bounds__(256) gather50(const float* __restrict__ x) {
    int node = (blockIdx.x * blockDim.x + threadIdx.x) >> 5;
    int lane = threadIdx.x & 31;
    if (node >= NN) return;
    int deg = g_cnt[node];
    deg = (deg > CAP) ? CAP : deg;
    const int* adj = g_badj + node * CAP;
    int c1 = 32 + lane;
    bool has1 = c1 < FIN;

    float m0 = -FLT_MAX, m1 = -FLT_MAX;
    for (int p = 0; p < deg; ++p) {
        const float* xs = x + adj[p] * FIN;
        m0 = fmaxf(m0, xs[lane]);
        if (has1) m1 = fmaxf(m1, xs[c1]);
    }
    if (deg == 0) { m0 = 0.0f; m1 = 0.0f; }
    g_agg1[node * FIN + lane] = m0;
    if (has1) g_agg1[node * FIN + c1] = m1;
}

// ---------------- gather-max d=32 -> g_agg ----------------
__global__ void __launch_bounds__(256) gather32(const float* __restrict__ hin) {
    int node = (blockIdx.x * blockDim.x + threadIdx.x) >> 5;
    int lane = threadIdx.x & 31;
    if (node >= NN) return;
    int deg = g_cnt[node];
    deg = (deg > CAP) ? CAP : deg;
    const int* adj = g_badj + node * CAP;

    float ma = -FLT_MAX, mb = -FLT_MAX;
    int p = 0;
    for (; p + 2 <= deg; p += 2) {
        ma = fmaxf(ma, hin[(adj[p]     << 5) + lane]);
        mb = fmaxf(mb, hin[(adj[p + 1] << 5) + lane]);
    }
    if (p < deg) ma = fmaxf(ma, hin[(adj[p] << 5) + lane]);
    float m = fmaxf(ma, mb);
    if (deg == 0) m = 0.0f;
    g_agg[(node << 5) + lane] = m;
}

// ---------------- GEMM layer 1 (f32x2): tile 128 nodes (64 pairs), K=100 ----------------
// thread = 2 pairs x 4 cols; sA float2[64][101]; sW2 float2[100*32] (w duplicated)
#define G1_PITCH 101
__global__ void __launch_bounds__(256) gemm1(const float* __restrict__ x,
                                             const float* __restrict__ Wl,
                                             const float* __restrict__ bl,
                                             const float* __restrict__ Wr,
                                             float* __restrict__ out) {
    extern __shared__ float2 smf2[];
    float2* sA = smf2;                         // 64 * 101
    float2* sW2 = smf2 + 64 * G1_PITCH;        // 100 * 32
    float2* sb2 = sW2 + 100 * 32;              // 32
    float* sAf = (float*)sA;
    int tid = threadIdx.x;
    int node0 = blockIdx.x * 128;

    for (int i = tid; i < 100 * 32; i += 256) {
        int k = i >> 5, c = i & 31;
        float v = (k < FIN) ? Wl[k * 32 + c] : Wr[(k - FIN) * 32 + c];
        sW2[i] = make_float2(v, v);
    }
    if (tid < 32) sb2[tid] = make_float2(bl[tid], bl[tid]);
    for (int i = tid; i < 128 * 100; i += 256) {
        int n = i / 100, k = i - n * 100;
        int gn = node0 + n;
        float v = 0.0f;
        if (gn < NN) v = (k < FIN) ? g_agg1[gn * FIN + k] : x[gn * FIN + (k - FIN)];
        sAf[((n >> 1) * G1_PITCH + k) * 2 + (n & 1)] = v;
    }
    __syncthreads();

    int c_grp = tid & 7;
    int p_grp = tid >> 3;           // 2 pairs: p_grp*2, p_grp*2+1
    const u64* a0p = (const u64*)&sA[(p_grp * 2 + 0) * G1_PITCH];
    const u64* a1p = (const u64*)&sA[(p_grp * 2 + 1) * G1_PITCH];

    u64 bias[4];
    {
        const u64* bp = (const u64*)&sb2[c_grp * 4];
        bias[0] = bp[0]; bias[1] = bp[1]; bias[2] = bp[2]; bias[3] = bp[3];
    }
    u64 acc[2][4];
#pragma unroll
    for (int j = 0; j < 4; j++) { acc[0][j] = bias[j]; acc[1][j] = bias[j]; }

#pragma unroll 4
    for (int k = 0; k < 100; k++) {
        const double2* wrow = (const double2*)(sW2 + k * 32 + c_grp * 4);
        double2 wA = wrow[0];
        double2 wB = wrow[1];
        u64 w0 = __double_as_longlong(wA.x);
        u64 w1 = __double_as_longlong(wA.y);
        u64 w2 = __double_as_longlong(wB.x);
        u64 w3 = __double_as_longlong(wB.y);
        u64 a0 = a0p[k];
        u64 a1 = a1p[k];
        acc[0][0] = ffma2(a0, w0, acc[0][0]);
        acc[0][1] = ffma2(a0, w1, acc[0][1]);
        acc[0][2] = ffma2(a0, w2, acc[0][2]);
        acc[0][3] = ffma2(a0, w3, acc[0][3]);
        acc[1][0] = ffma2(a1, w0, acc[1][0]);
        acc[1][1] = ffma2(a1, w1, acc[1][1]);
        acc[1][2] = ffma2(a1, w2, acc[1][2]);
        acc[1][3] = ffma2(a1, w3, acc[1][3]);
    }

#pragma unroll
    for (int i = 0; i < 2; i++) {
        int g0 = node0 + (p_grp * 2 + i) * 2;   // even node
        int g1 = g0 + 1;                        // odd node
        float e0, o0, e1, o1, e2, o2, e3, o3;
        unpack2(acc[i][0], e0, o0);
        unpack2(acc[i][1], e1, o1);
        unpack2(acc[i][2], e2, o2);
        unpack2(acc[i][3], e3, o3);
        if (g0 < NN) {
            float4 r = make_float4(fmaxf(e0, 0.f), fmaxf(e1, 0.f), fmaxf(e2, 0.f), fmaxf(e3, 0.f));
            *(float4*)&out[g0 * 32 + c_grp * 4] = r;
        }
        if (g1 < NN) {
            float4 r = make_float4(fmaxf(o0, 0.f), fmaxf(o1, 0.f), fmaxf(o2, 0.f), fmaxf(o3, 0.f));
            *(float4*)&out[g1 * 32 + c_grp * 4] = r;
        }
    }
}

// ---------------- GEMM layers 2/3 (f32x2): tile 256 nodes (128 pairs), K=64 ----------------
// thread = 4 pairs x 4 cols; sA float2[128][65]; sW2 float2[64*32]
#define G2_PITCH 65
template <bool FINAL>
__global__ void __launch_bounds__(256) gemm23(const float* __restrict__ self,
                                              const float* __restrict__ Wl,
                                              const float* __restrict__ bl,
                                              const float* __restrict__ Wr,
                                              float* __restrict__ out) {
    extern __shared__ float2 smf2[];
    float2* sA = smf2;                          // 128 * 65
    float2* sW2 = smf2 + 128 * G2_PITCH;        // 64 * 32
    float2* sb2 = sW2 + 64 * 32;                // 32
    float* sAf = (float*)sA;
    int tid = threadIdx.x;
    int node0 = blockIdx.x * 256;

    for (int i = tid; i < 64 * 32; i += 256) {
        int k = i >> 5, c = i & 31;
        float v = (k < CC) ? Wl[k * 32 + c] : Wr[(k - CC) * 32 + c];
        sW2[i] = make_float2(v, v);
    }
    if (tid < 32) sb2[tid] = make_float2(bl[tid], bl[tid]);
    for (int i = tid; i < 256 * 64; i += 256) {
        int n = i >> 6, k = i & 63;
        int gn = node0 + n;
        float v = 0.0f;
        if (gn < NN) v = (k < CC) ? g_agg[(gn << 5) + k] : self[(gn << 5) + (k - CC)];
        sAf[((n >> 1) * G2_PITCH + k) * 2 + (n & 1)] = v;
    }
    __syncthreads();

    int c_grp = tid & 7;
    int p_grp = tid >> 3;          // 4 pairs: p_grp*4 .. +3
    u64 bias[4];
    {
        const u64* bp = (const u64*)&sb2[c_grp * 4];
        bias[0] = bp[0]; bias[1] = bp[1]; bias[2] = bp[2]; bias[3] = bp[3];
    }
    u64 acc[4][4];
#pragma unroll
    for (int i = 0; i < 4; i++)
#pragma unroll
        for (int j = 0; j < 4; j++) acc[i][j] = bias[j];

    const u64* ap = (const u64*)&sA[p_grp * 4 * G2_PITCH];

#pragma unroll 4
    for (int k = 0; k < 64; k++) {
        const double2* wrow = (const double2*)(sW2 + k * 32 + c_grp * 4);
        double2 wA = wrow[0];
        double2 wB = wrow[1];
        u64 w0 = __double_as_longlong(wA.x);
        u64 w1 = __double_as_longlong(wA.y);
        u64 w2 = __double_as_longlong(wB.x);
        u64 w3 = __double_as_longlong(wB.y);
#pragma unroll
        for (int i = 0; i < 4; i++) {
            u64 a = ap[i * G2_PITCH + k];
            acc[i][0] = ffma2(a, w0, acc[i][0]);
            acc[i][1] = ffma2(a, w1, acc[i][1]);
            acc[i][2] = ffma2(a, w2, acc[i][2]);
            acc[i][3] = ffma2(a, w3, acc[i][3]);
        }
    }

#pragma unroll
    for (int i = 0; i < 4; i++) {
        int g0 = node0 + (p_grp * 4 + i) * 2;
        int g1 = g0 + 1;
        float e0, o0, e1, o1, e2, o2, e3, o3;
        unpack2(acc[i][0], e0, o0);
        unpack2(acc[i][1], e1, o1);
        unpack2(acc[i][2], e2, o2);
        unpack2(acc[i][3], e3, o3);
        if (!FINAL) {
            if (g0 < NN) {
                float4 r = make_float4(fmaxf(e0, 0.f), fmaxf(e1, 0.f), fmaxf(e2, 0.f), fmaxf(e3, 0.f));
                *(float4*)&out[(g0 << 5) + c_grp * 4] = r;
            }
            if (g1 < NN) {
                float4 r = make_float4(fmaxf(o0, 0.f), fmaxf(o1, 0.f), fmaxf(o2, 0.f), fmaxf(o3, 0.f));
                *(float4*)&out[(g1 << 5) + c_grp * 4] = r;
            }
        } else {
            // even node
            float mx = fmaxf(fmaxf(e0, e1), fmaxf(e2, e3));
#pragma unroll
            for (int o = 1; o < 8; o <<= 1) mx = fmaxf(mx, __shfl_xor_sync(0xffffffff, mx, o));
            float s = expf(e0 - mx) + expf(e1 - mx) + expf(e2 - mx) + expf(e3 - mx);
#pragma unroll
            for (int o = 1; o < 8; o <<= 1) s += __shfl_xor_sync(0xffffffff, s, o);
            float l = mx + logf(s);
            if (g0 < NN) {
                float4 r = make_float4(e0 - l, e1 - l, e2 - l, e3 - l);
                *(float4*)&out[(g0 << 5) + c_grp * 4] = r;
            }
            // odd node
            float mx2 = fmaxf(fmaxf(o0, o1), fmaxf(o2, o3));
#pragma unroll
            for (int o = 1; o < 8; o <<= 1) mx2 = fmaxf(mx2, __shfl_xor_sync(0xffffffff, mx2, o));
            float s2 = expf(o0 - mx2) + expf(o1 - mx2) + expf(o2 - mx2) + expf(o3 - mx2);
#pragma unroll
            for (int o = 1; o < 8; o <<= 1) s2 += __shfl_xor_sync(0xffffffff, s2, o);
            float l2 = mx2 + logf(s2);
            if (g1 < NN) {
                float4 r = make_float4(o0 - l2, o1 - l2, o2 - l2, o3 - l2);
                *(float4*)&out[(g1 << 5) + c_grp * 4] = r;
            }
        }
    }
}

extern "C" void kernel_launch(void* const* d_in, const int* in_sizes, int n_in,
                              void* d_out, int out_size) {
    const float* x = (const float*)d_in[0];
    const int* ei = (const int*)d_in[1];
    const float* Wl1 = (const float*)d_in[2];
    const float* bl1 = (const float*)d_in[3];
    const float* Wr1 = (const float*)d_in[4];
    const float* Wl2 = (const float*)d_in[5];
    const float* bl2 = (const float*)d_in[6];
    const float* Wr2 = (const float*)d_in[7];
    const float* Wl3 = (const float*)d_in[8];
    const float* bl3 = (const float*)d_in[9];
    const float* Wr3 = (const float*)d_in[10];
    float* out = (float*)d_out;

    int E = in_sizes[1] / 2;

    const int TB = 256;
    int nblk = (NN + TB - 1) / TB;
    int eblk = (E + TB - 1) / TB;
    int gblk = (NN * 32 + TB - 1) / TB;
    int g1blk = (NN + 127) / 128;
    int g23blk = (NN + 255) / 256;

    size_t sm1 = (64 * G1_PITCH + 100 * 32 + 32) * sizeof(float2);    // ~77.5 KB
    size_t sm23 = (128 * G2_PITCH + 64 * 32 + 32) * sizeof(float2);   // ~83.2 KB
    cudaFuncSetAttribute(gemm1, cudaFuncAttributeMaxDynamicSharedMemorySize, (int)sm1);
    cudaFuncSetAttribute(gemm23<false>, cudaFuncAttributeMaxDynamicSharedMemorySize, (int)sm23);
    cudaFuncSetAttribute(gemm23<true>, cudaFuncAttributeMaxDynamicSharedMemorySize, (int)sm23);

    float* ha;  cudaGetSymbolAddress((void**)&ha, g_ha);
    float* hb;  cudaGetSymbolAddress((void**)&hb, g_hb);

    zero_cnt<<<nblk, TB>>>();
    bucket_scatter<<<eblk, TB>>>(ei, E);

    gather50<<<gblk, TB>>>(x);
    gemm1<<<g1blk, TB, sm1>>>(x, Wl1, bl1, Wr1, ha);

    gather32<<<gblk, TB>>>(ha);
    gemm23<false><<<g23blk, TB, sm23>>>(ha, Wl2, bl2, Wr2, hb);

    gather32<<<gblk, TB>>>(hb);
    gemm23<true><<<g23blk, TB, sm23>>>(hb, Wl3, bl3, Wr3, out);
}

// round 15
// speedup vs baseline: 1.7131x; 1.7131x over previous
#include <cuda_runtime.h>
#include <cuda_bf16.h>
#include <math.h>
#include <float.h>

#define NN 100000
#define FIN 50
#define CC 32
#define CAP 96

// ---------------- scratch ----------------
__device__ int g_cnt[NN];
__device__ int g_badj[NN * CAP];
__device__ float g_agg1[NN * FIN];
__device__ float g_agg[NN * CC];
__device__ float g_ha[NN * CC];
__device__ float g_hb[NN * CC];

__global__ void __launch_bounds__(256) zero_cnt() {
    int i = blockIdx.x * blockDim.x + threadIdx.x;
    if (i < NN) g_cnt[i] = 0;
}

__global__ void __launch_bounds__(256) bucket_scatter(const int* __restrict__ ei, int E) {
    int e = blockIdx.x * blockDim.x + threadIdx.x;
    if (e >= E) return;
    int s = ei[e];
    int d = ei[E + e];
    int pos = atomicAdd(&g_cnt[d], 1);
    if (pos < CAP) g_badj[d * CAP + pos] = s;
}

// ---------------- gather-max d=50 -> g_agg1 ----------------
__global__ void __launch_bounds__(256) gather50(const float* __restrict__ x) {
    int node = (blockIdx.x * blockDim.x + threadIdx.x) >> 5;
    int lane = threadIdx.x & 31;
    if (node >= NN) return;
    int deg = g_cnt[node];
    deg = (deg > CAP) ? CAP : deg;
    const int* adj = g_badj + node * CAP;
    int c1 = 32 + lane;
    bool has1 = c1 < FIN;

    float m0 = -FLT_MAX, m1 = -FLT_MAX;
    for (int p = 0; p < deg; ++p) {
        const float* xs = x + adj[p] * FIN;
        m0 = fmaxf(m0, xs[lane]);
        if (has1) m1 = fmaxf(m1, xs[c1]);
    }
    if (deg == 0) { m0 = 0.0f; m1 = 0.0f; }
    g_agg1[node * FIN + lane] = m0;
    if (has1) g_agg1[node * FIN + c1] = m1;
}

// ---------------- gather-max d=32 -> g_agg ----------------
__global__ void __launch_bounds__(256) gather32(const float* __restrict__ hin) {
    int node = (blockIdx.x * blockDim.x + threadIdx.x) >> 5;
    int lane = threadIdx.x & 31;
    if (node >= NN) return;
    int deg = g_cnt[node];
    deg = (deg > CAP) ? CAP : deg;
    const int* adj = g_badj + node * CAP;

    float ma = -FLT_MAX, mb = -FLT_MAX;
    int p = 0;
    for (; p + 2 <= deg; p += 2) {
        ma = fmaxf(ma, hin[(adj[p]     << 5) + lane]);
        mb = fmaxf(mb, hin[(adj[p + 1] << 5) + lane]);
    }
    if (p < deg) ma = fmaxf(ma, hin[(adj[p] << 5) + lane]);
    float m = fmaxf(ma, mb);
    if (deg == 0) m = 0.0f;
    g_agg[(node << 5) + lane] = m;
}

// ---------------- GEMM layer 1: C = agg1@Wl + x@Wr + b, relu ----------------
// tile 256 nodes x 32 cols; thread = 8 nodes x 4 cols; K=100; dyn smem ~116 KB
#define G1_PITCH 101
__global__ void __launch_bounds__(256) gemm1(const float* __restrict__ x,
                                             const float* __restrict__ Wl,
                                             const float* __restrict__ bl,
                                             const float* __restrict__ Wr,
                                             float* __restrict__ out) {
    extern __shared__ float sm[];
    float* sA = sm;                       // 256 * 101
    float* sW = sm + 256 * G1_PITCH;      // 100 * 32
    float* sb = sW + 100 * 32;            // 32
    int tid = threadIdx.x;
    int node0 = blockIdx.x * 256;

    for (int i = tid; i < FIN * 32; i += 256) {
        sW[i] = Wl[i];
        sW[FIN * 32 + i] = Wr[i];
    }
    if (tid < 32) sb[tid] = bl[tid];
    for (int i = tid; i < 256 * FIN; i += 256) {
        int n = i / FIN, k = i - n * FIN;
        int gn = node0 + n;
        float v1 = 0.0f, v2 = 0.0f;
        if (gn < NN) { v1 = g_agg1[gn * FIN + k]; v2 = x[gn * FIN + k]; }
        sA[n * G1_PITCH + k] = v1;
        sA[n * G1_PITCH + FIN + k] = v2;
    }
    __syncthreads();

    int c_grp = tid & 7;       // 4 cols
    int n_grp = tid >> 3;      // 8 nodes
    float4 b4 = *(const float4*)&sb[c_grp * 4];
    float acc[8][4];
#pragma unroll
    for (int i = 0; i < 8; i++) {
        acc[i][0] = b4.x; acc[i][1] = b4.y; acc[i][2] = b4.z; acc[i][3] = b4.w;
    }
    const float* ap = &sA[n_grp * 8 * G1_PITCH];

#pragma unroll 4
    for (int k = 0; k < 100; k++) {
        float4 w = *(const float4*)&sW[k * 32 + c_grp * 4];
#pragma unroll
        for (int i = 0; i < 8; i++) {
            float v = ap[i * G1_PITCH + k];
            acc[i][0] += v * w.x; acc[i][1] += v * w.y;
            acc[i][2] += v * w.z; acc[i][3] += v * w.w;
        }
    }

#pragma unroll
    for (int i = 0; i < 8; i++) {
        int gn = node0 + n_grp * 8 + i;
        if (gn < NN) {
            float4 r;
            r.x = fmaxf(acc[i][0], 0.0f);
            r.y = fmaxf(acc[i][1], 0.0f);
            r.z = fmaxf(acc[i][2], 0.0f);
            r.w = fmaxf(acc[i][3], 0.0f);
            *(float4*)&out[gn * 32 + c_grp * 4] = r;
        }
    }
}

// ---------------- GEMM layers 2/3: tile 256 nodes; thread = 8 nodes x 4 cols ----------------
#define G2_PITCH 65
template <bool FINAL>
__global__ void __launch_bounds__(256) gemm23(const float* __restrict__ self,
                                              const float* __restrict__ Wl,
                                              const float* __restrict__ bl,
                                              const float* __restrict__ Wr,
                                              float* __restrict__ out) {
    extern __shared__ float sm[];
    float* sA = sm;                       // 256 * 65
    float* sW = sm + 256 * G2_PITCH;      // 64 * 32
    float* sb = sW + 64 * 32;             // 32
    int tid = threadIdx.x;
    int node0 = blockIdx.x * 256;

    for (int i = tid; i < CC * 32; i += 256) {
        sW[i] = Wl[i];
        sW[CC * 32 + i] = Wr[i];
    }
    if (tid < 32) sb[tid] = bl[tid];
    for (int i = tid; i < 256 * CC; i += 256) {
        int n = i >> 5, k = i & 31;
        int gn = node0 + n;
        float v1 = 0.0f, v2 = 0.0f;
        if (gn < NN) { v1 = g_agg[(gn << 5) + k]; v2 = self[(gn << 5) + k]; }
        sA[n * G2_PITCH + k] = v1;
        sA[n * G2_PITCH + CC + k] = v2;
    }
    __syncthreads();

    int c_grp = tid & 7;
    int n_grp = tid >> 3;      // 8 nodes each
    float4 b4 = *(const float4*)&sb[c_grp * 4];
    float acc[8][4];
#pragma unroll
    for (int i = 0; i < 8; i++) {
        acc[i][0] = b4.x; acc[i][1] = b4.y; acc[i][2] = b4.z; acc[i][3] = b4.w;
    }
    const float* ap = &sA[n_grp * 8 * G2_PITCH];

#pragma unroll 4
    for (int k = 0; k < 64; k++) {
        float4 w = *(const float4*)&sW[k * 32 + c_grp * 4];
#pragma unroll
        for (int i = 0; i < 8; i++) {
            float v = ap[i * G2_PITCH + k];
            acc[i][0] += v * w.x; acc[i][1] += v * w.y;
            acc[i][2] += v * w.z; acc[i][3] += v * w.w;
        }
    }

#pragma unroll
    for (int i = 0; i < 8; i++) {
        int gn = node0 + n_grp * 8 + i;
        if (!FINAL) {
            if (gn < NN) {
                float4 r;
                r.x = fmaxf(acc[i][0], 0.0f);
                r.y = fmaxf(acc[i][1], 0.0f);
                r.z = fmaxf(acc[i][2], 0.0f);
                r.w = fmaxf(acc[i][3], 0.0f);
                *(float4*)&out[(gn << 5) + c_grp * 4] = r;
            }
        } else {
            float mx = fmaxf(fmaxf(acc[i][0], acc[i][1]), fmaxf(acc[i][2], acc[i][3]));
#pragma unroll
            for (int o = 1; o < 8; o <<= 1) mx = fmaxf(mx, __shfl_xor_sync(0xffffffff, mx, o));
            float s = expf(acc[i][0] - mx) + expf(acc[i][1] - mx)
                    + expf(acc[i][2] - mx) + expf(acc[i][3] - mx);
#pragma unroll
            for (int o = 1; o < 8; o <<= 1) s += __shfl_xor_sync(0xffffffff, s, o);
            float l = mx + logf(s);
            if (gn < NN) {
                float4 r;
                r.x = acc[i][0] - l; r.y = acc[i][1] - l;
                r.z = acc[i][2] - l; r.w = acc[i][3] - l;
                *(float4*)&out[(gn << 5) + c_grp * 4] = r;
            }
        }
    }
}

extern "C" void kernel_launch(void* const* d_in, const int* in_sizes, int n_in,
                              void* d_out, int out_size) {
    const float* x = (const float*)d_in[0];
    const int* ei = (const int*)d_in[1];
    const float* Wl1 = (const float*)d_in[2];
    const float* bl1 = (const float*)d_in[3];
    const float* Wr1 = (const float*)d_in[4];
    const float* Wl2 = (const float*)d_in[5];
    const float* bl2 = (const float*)d_in[6];
    const float* Wr2 = (const float*)d_in[7];
    const float* Wl3 = (const float*)d_in[8];
    const float* bl3 = (const float*)d_in[9];
    const float* Wr3 = (const float*)d_in[10];
    float* out = (float*)d_out;

    int E = in_sizes[1] / 2;

    const int TB = 256;
    int nblk = (NN + TB - 1) / TB;
    int eblk = (E + TB - 1) / TB;
    int gblk = (NN * 32 + TB - 1) / TB;
    int g1blk = (NN + 255) / 256;
    int g23blk = (NN + 255) / 256;

    size_t sm1 = (256 * G1_PITCH + 100 * 32 + 32) * sizeof(float);      // ~116 KB
    size_t sm23 = (256 * G2_PITCH + 64 * 32 + 32) * sizeof(float);      // ~74.9 KB
    cudaFuncSetAttribute(gemm1, cudaFuncAttributeMaxDynamicSharedMemorySize, (int)sm1);
    cudaFuncSetAttribute(gemm23<false>, cudaFuncAttributeMaxDynamicSharedMemorySize, (int)sm23);
    cudaFuncSetAttribute(gemm23<true>, cudaFuncAttributeMaxDynamicSharedMemorySize, (int)sm23);

    float* ha;  cudaGetSymbolAddress((void**)&ha, g_ha);
    float* hb;  cudaGetSymbolAddress((void**)&hb, g_hb);

    zero_cnt<<<nblk, TB>>>();
    bucket_scatter<<<eblk, TB>>>(ei, E);

    gather50<<<gblk, TB>>>(x);
    gemm1<<<g1blk, TB, sm1>>>(x, Wl1, bl1, Wr1, ha);

    gather32<<<gblk, TB>>>(ha);
    gemm23<false><<<g23blk, TB, sm23>>>(ha, Wl2, bl2, Wr2, hb);

    gather32<<<gblk, TB>>>(hb);
    gemm23<true><<<g23blk, TB, sm23>>>(hb, Wl3, bl3, Wr3, out);
}